// round 13
// baseline (speedup 1.0000x reference)
#include <cuda_runtime.h>
#include <math.h>

// Problem constants
#define NB   64      // batch N
#define TT   1024    // time steps
#define DD   512     // input dim
#define HHD  512     // hidden dim
#define FH   2048    // 4*H

// ---------------- device scratch (allocation-free rule: __device__ globals) ----
__device__ __align__(16) float g_xw[NB * TT * FH];   // xW+b, layout (t, n, col)
__device__ __align__(16) float g_WhT[FH * HHD];      // Wh transposed: (2048, 512)
__device__ __align__(16) float g_h[2][NB * HHD];     // double-buffered hidden state
__device__ unsigned g_count;                         // grid barrier counter

// packed fp32x2 ops (sm_100+)
__device__ __forceinline__ void ffma2(unsigned long long& d,
                                      unsigned long long a,
                                      unsigned long long b) {
    asm("fma.rn.f32x2 %0, %1, %2, %0;" : "+l"(d) : "l"(a), "l"(b));
}
__device__ __forceinline__ void fadd2(unsigned long long& d,
                                      unsigned long long a) {
    asm("add.rn.f32x2 %0, %0, %1;" : "+l"(d) : "l"(a));
}
__device__ __forceinline__ unsigned long long pack2(float x) {
    unsigned long long r;
    asm("mov.b64 %0, {%1, %1};" : "=l"(r) : "f"(x));
    return r;
}

// MUFU-based activations (EX2 + RCP), ~1e-6 accuracy, saturate cleanly.
__device__ __forceinline__ float fsig(float x) {
    return __fdividef(1.f, 1.f + __expf(-x));
}
__device__ __forceinline__ float ftanhf(float x) {
    return 1.f - __fdividef(2.f, __expf(2.f * x) + 1.f);
}

// ---------------- init: reset barrier counter + load h0 -----------------------
__global__ void init_kernel(const float* __restrict__ h0) {
    int i = blockIdx.x * blockDim.x + threadIdx.x;
    if (i == 0) g_count = 0u;
    if (i < NB * HHD) g_h[0][i] = h0[i];
}

// ---------------- transpose Wh (512,2048) -> WhT (2048,512) -------------------
__global__ void transpose_wh(const float* __restrict__ Wh) {
    int idx = blockIdx.x * blockDim.x + threadIdx.x;   // coalesced read
    int k = idx >> 11;
    int col = idx & 2047;
    g_WhT[col * HHD + k] = Wh[idx];
}

// ---------------- phase 1: xW = X @ Wx + b  (65536x2048x512 SGEMM) ------------
// (unchanged from R12 — passing)
__global__ __launch_bounds__(256, 2)
void gemm_xw(const float* __restrict__ X, const float* __restrict__ Wx,
             const float* __restrict__ bias) {
    __shared__ __align__(16) float As[8][128];
    __shared__ __align__(16) float Bs[8][128];

    const int tid  = threadIdx.x;
    const int row0 = blockIdx.y * 128;
    const int col0 = blockIdx.x * 128;

    const int aRow = tid >> 1;
    const int aCol = (tid & 1) * 4;
    const int bRow = tid >> 5;
    const int bCol = (tid & 31) * 4;

    const int tx = tid & 15;
    const int ty = tid >> 4;

    const float* Ap = X  + (size_t)(row0 + aRow) * DD + aCol;
    const float* Bp = Wx + (size_t)bRow * FH + col0 + bCol;

    unsigned long long acc2[8][4];
#pragma unroll
    for (int i = 0; i < 8; i++)
#pragma unroll
        for (int p = 0; p < 4; p++) acc2[i][p] = 0ull;

    for (int k0 = 0; k0 < DD; k0 += 8) {
        float4 av = __ldg((const float4*)(Ap + k0));
        float4 bv = __ldg((const float4*)(Bp + (size_t)k0 * FH));
        As[aCol + 0][aRow] = av.x;
        As[aCol + 1][aRow] = av.y;
        As[aCol + 2][aRow] = av.z;
        As[aCol + 3][aRow] = av.w;
        *(float4*)&Bs[bRow][bCol] = bv;
        __syncthreads();
#pragma unroll
        for (int k = 0; k < 8; k++) {
            float4 a0 = *(const float4*)&As[k][ty * 8];
            float4 a1 = *(const float4*)&As[k][ty * 8 + 4];
            ulonglong2 bp0 = *(const ulonglong2*)&Bs[k][tx * 4];
            ulonglong2 bp1 = *(const ulonglong2*)&Bs[k][64 + tx * 4];
            float ar[8] = {a0.x, a0.y, a0.z, a0.w, a1.x, a1.y, a1.z, a1.w};
#pragma unroll
            for (int i = 0; i < 8; i++) {
                unsigned long long aa = pack2(ar[i]);
                ffma2(acc2[i][0], aa, bp0.x);
                ffma2(acc2[i][1], aa, bp0.y);
                ffma2(acc2[i][2], aa, bp1.x);
                ffma2(acc2[i][3], aa, bp1.y);
            }
        }
        __syncthreads();
    }

    float4 bb0 = __ldg((const float4*)&bias[col0 + tx * 4]);
    float4 bb1 = __ldg((const float4*)&bias[col0 + 64 + tx * 4]);
#pragma unroll
    for (int i = 0; i < 8; i++) {
        int m  = row0 + ty * 8 + i;
        int tt = m & (TT - 1);
        int nn = m >> 10;
        float* orow = g_xw + ((size_t)(tt * NB + nn)) * FH + col0;
        union { unsigned long long u; float2 f; } p0, p1, p2, p3;
        p0.u = acc2[i][0]; p1.u = acc2[i][1];
        p2.u = acc2[i][2]; p3.u = acc2[i][3];
        float4 v0 = make_float4(p0.f.x + bb0.x, p0.f.y + bb0.y,
                                p1.f.x + bb0.z, p1.f.y + bb0.w);
        float4 v1 = make_float4(p2.f.x + bb1.x, p2.f.y + bb1.y,
                                p3.f.x + bb1.z, p3.f.y + bb1.w);
        *(float4*)(orow + tx * 4)      = v0;
        *(float4*)(orow + 64 + tx * 4) = v1;
    }
}

// ---------------- phase 2: persistent LSTM recurrence -------------------------
// 128 CTAs x 512 threads. CTA b owns gate-local columns j0..j0+3 across all 4
// gates, all 64 batch rows. Thread (nl2 = (tid>>2)&31, jj = tid&3) owns TWO
// outputs: rows nl2 and nl2+32, column j0+jj, ALL 4 gates => 8 packed
// accumulators fed by 6 LDS.128 per 4k (h row pair nl2/nl2+32 keeps both LDS
// patterns bank-conflict-free at stride 516). z = tid>>7 splits k into
// quarters; z>0 dump partials to smem, z=0 combines + runs activations
// (R11-identical math, MUFU intrinsics) and owns c for both rows.
#define HSTRIDE 516                               // 512 + 4 pad
#define HTILE   (NB * HSTRIDE)                    // 33024 floats
#define WTILE   (16 * HSTRIDE)                    // 8256 floats
#define REDU64  (3 * 128 * 8)                     // 3072 u64 = 24KB reduction
#define LSTM_SMEM_BYTES ((HTILE + WTILE) * 4 + REDU64 * 8)   // 189,696 B

__global__ __launch_bounds__(512, 1)
void lstm_kernel(float* __restrict__ out) {
    extern __shared__ float sm[];
    float* sh = sm;                         // h tile [64][516]
    float* sw = sm + HTILE;                 // W tile [16][516], row = gate*4+col
    unsigned long long* red =
        (unsigned long long*)(sm + HTILE + WTILE);

    const int tid = threadIdx.x;
    const int z   = tid >> 7;          // k-quarter 0..3
    const int idx = tid & 127;         // logical thread within quarter
    const int nl2 = (tid >> 2) & 31;   // row-pair id
    const int jj  = tid & 3;           // column within CTA's 4
    const int n0  = nl2, n1 = nl2 + 32;
    const int j0  = blockIdx.x * 4;
    const int j   = j0 + jj;

    // ---- stage Wh slice once: smem row r <-> (gate = r>>2, col = r&3) ----
    for (int i = tid; i < 2048; i += 512) {        // 16 rows x 128 float4
        int r  = i >> 7;
        int kq = (i & 127) * 4;
        int G  = (r >> 2) * HHD + j0 + (r & 3);    // WhT row (a-column)
        float4 v = __ldg((const float4*)&g_WhT[(size_t)G * HHD + kq]);
        *(float4*)&sw[r * HSTRIDE + kq] = v;
    }

    // per-thread pointers into own k-quarter (z*128 floats = z*32 ulonglong2)
    const ulonglong2* hp0 = (const ulonglong2*)(sh + n0 * HSTRIDE) + z * 32;
    const ulonglong2* hp1 = (const ulonglong2*)(sh + n1 * HSTRIDE) + z * 32;
    const ulonglong2* w0 = (const ulonglong2*)(sw + (0 * 4 + jj) * HSTRIDE) + z * 32;
    const ulonglong2* w1 = (const ulonglong2*)(sw + (1 * 4 + jj) * HSTRIDE) + z * 32;
    const ulonglong2* w2 = (const ulonglong2*)(sw + (2 * 4 + jj) * HSTRIDE) + z * 32;
    const ulonglong2* w3 = (const ulonglong2*)(sw + (3 * 4 + jj) * HSTRIDE) + z * 32;

    float c0 = 0.f, c1 = 0.f;
    int nb = 0;

    for (int t = 0; t < TT; t++) {
        // xW prefetch for both rows (activation quarter only)
        float xi0 = 0.f, xf0 = 0.f, xo0 = 0.f, xg0 = 0.f;
        float xi1 = 0.f, xf1 = 0.f, xo1 = 0.f, xg1 = 0.f;
        if (z == 0) {
            const size_t xa = ((size_t)(t * NB + n0)) * FH + j;
            const size_t xbq = ((size_t)(t * NB + n1)) * FH + j;
            xi0 = __ldg(&g_xw[xa]);          xi1 = __ldg(&g_xw[xbq]);
            xf0 = __ldg(&g_xw[xa + 512]);    xf1 = __ldg(&g_xw[xbq + 512]);
            xo0 = __ldg(&g_xw[xa + 1024]);   xo1 = __ldg(&g_xw[xbq + 1024]);
            xg0 = __ldg(&g_xw[xa + 1536]);   xg1 = __ldg(&g_xw[xbq + 1536]);
        }

        // ---- stage full h into smem (coalesced ld.cg, high MLP) ----
        const float* hsrc = g_h[nb];
#pragma unroll
        for (int u = 0; u < 16; u++) {
            int i = tid + u * 512;                    // float4 index 0..8191
            float4 v = __ldcg((const float4*)&hsrc[i * 4]);
            *(float4*)&sh[(i >> 7) * HSTRIDE + (i & 127) * 4] = v;
        }
        __syncthreads();

        // ---- quarter-k dot: 6 LDS.128 + 16 FFMA2 per 4k, 32 iters ----
        unsigned long long a00 = 0ull, a10 = 0ull, a20 = 0ull, a30 = 0ull;
        unsigned long long a01 = 0ull, a11 = 0ull, a21 = 0ull, a31 = 0ull;
#pragma unroll 8
        for (int kq = 0; kq < 32; kq++) {
            ulonglong2 h0 = hp0[kq];
            ulonglong2 h1 = hp1[kq];
            ulonglong2 v0 = w0[kq];
            ulonglong2 v1 = w1[kq];
            ulonglong2 v2 = w2[kq];
            ulonglong2 v3 = w3[kq];
            ffma2(a00, h0.x, v0.x); ffma2(a00, h0.y, v0.y);
            ffma2(a10, h0.x, v1.x); ffma2(a10, h0.y, v1.y);
            ffma2(a20, h0.x, v2.x); ffma2(a20, h0.y, v2.y);
            ffma2(a30, h0.x, v3.x); ffma2(a30, h0.y, v3.y);
            ffma2(a01, h1.x, v0.x); ffma2(a01, h1.y, v0.y);
            ffma2(a11, h1.x, v1.x); ffma2(a11, h1.y, v1.y);
            ffma2(a21, h1.x, v2.x); ffma2(a21, h1.y, v2.y);
            ffma2(a31, h1.x, v3.x); ffma2(a31, h1.y, v3.y);
        }

        // ---- cross-quarter reduction (24KB smem region) ----
        if (z != 0) {
            unsigned long long* r8 = red + ((z - 1) * 128 + idx) * 8;
            ulonglong2* r2 = (ulonglong2*)r8;
            r2[0] = make_ulonglong2(a00, a10);
            r2[1] = make_ulonglong2(a20, a30);
            r2[2] = make_ulonglong2(a01, a11);
            r2[3] = make_ulonglong2(a21, a31);
        }
        __syncthreads();

        if (z == 0) {
#pragma unroll
            for (int zz = 0; zz < 3; zz++) {
                const ulonglong2* r2 =
                    (const ulonglong2*)(red + (zz * 128 + idx) * 8);
                ulonglong2 p0 = r2[0], p1 = r2[1], p2 = r2[2], p3 = r2[3];
                fadd2(a00, p0.x); fadd2(a10, p0.y);
                fadd2(a20, p1.x); fadd2(a30, p1.y);
                fadd2(a01, p2.x); fadd2(a11, p2.y);
                fadd2(a21, p3.x); fadd2(a31, p3.y);
            }
            union { unsigned long long u; float2 f; } q;
            // row n0 — gates [i,f,o,g], identical math to R11/R12
            q.u = a00; float ai0 = xi0 + q.f.x + q.f.y;
            q.u = a10; float af0 = xf0 + q.f.x + q.f.y;
            q.u = a20; float ao0 = xo0 + q.f.x + q.f.y;
            q.u = a30; float ag0 = xg0 + q.f.x + q.f.y;
            float ig = fsig(ai0), fg = fsig(af0), og = fsig(ao0);
            float gg = ftanhf(ag0);
            c0 = fg * c0 + ig * gg;
            float hn0 = og * ftanhf(c0);
            // row n1
            q.u = a01; float ai1 = xi1 + q.f.x + q.f.y;
            q.u = a11; float af1 = xf1 + q.f.x + q.f.y;
            q.u = a21; float ao1 = xo1 + q.f.x + q.f.y;
            q.u = a31; float ag1 = xg1 + q.f.x + q.f.y;
            float ig1 = fsig(ai1), fg1 = fsig(af1), og1 = fsig(ao1);
            float gg1 = ftanhf(ag1);
            c1 = fg1 * c1 + ig1 * gg1;
            float hn1 = og1 * ftanhf(c1);

            out[((size_t)n0 * TT + t) * HHD + j] = hn0;
            out[((size_t)n1 * TT + t) * HHD + j] = hn1;
            float* hdst = g_h[nb ^ 1];
            hdst[n0 * HHD + j] = hn0;
            hdst[n1 * HHD + j] = hn1;
        }

        // ---- global barrier: release fence + RED arrive + ld.cg spin ----
        __threadfence();            // release: h stores visible before arrive
        __syncthreads();
        if (tid == 0) {
            atomicAdd(&g_count, 1u);
            unsigned tgt = (unsigned)(t + 1) * (unsigned)gridDim.x;
            unsigned v;
            do {
                asm volatile("ld.global.cg.u32 %0, [%1];"
                             : "=r"(v) : "l"(&g_count) : "memory");
                if (v >= tgt) break;
                __nanosleep(64);
            } while (true);
        }
        __syncthreads();
        // no acquire fence needed: h staging uses ld.cg (L2-coherent),
        // xw/WhT are never rewritten during the kernel.
        nb ^= 1;
    }
}

// ---------------- launch ------------------------------------------------------
extern "C" void kernel_launch(void* const* d_in, const int* in_sizes, int n_in,
                              void* d_out, int out_size) {
    (void)in_sizes; (void)n_in; (void)out_size;
    const float* x  = (const float*)d_in[0];   // (64,1024,512)
    const float* h0 = (const float*)d_in[1];   // (64,512)
    const float* Wx = (const float*)d_in[2];   // (512,2048)
    const float* Wh = (const float*)d_in[3];   // (512,2048)
    const float* b  = (const float*)d_in[4];   // (2048)
    float* out = (float*)d_out;                // (64,1024,512) fp32

    cudaFuncSetAttribute(lstm_kernel,
                         cudaFuncAttributeMaxDynamicSharedMemorySize,
                         LSTM_SMEM_BYTES);

    init_kernel<<<128, 256>>>(h0);
    transpose_wh<<<(DD * FH) / 256, 256>>>(Wh);
    gemm_xw<<<dim3(FH / 128, (NB * TT) / 128), 256>>>(x, Wx, b);
    lstm_kernel<<<128, 512, LSTM_SMEM_BYTES>>>(out);
}

// round 14
// speedup vs baseline: 1.1125x; 1.1125x over previous
#include <cuda_runtime.h>
#include <math.h>

// Problem constants
#define NB   64      // batch N
#define TT   1024    // time steps
#define DD   512     // input dim
#define HHD  512     // hidden dim
#define FH   2048    // 4*H

// ---------------- device scratch (allocation-free rule: __device__ globals) ----
__device__ __align__(16) float g_xw[NB * TT * FH];   // xW+b, layout (t, n, col)
__device__ __align__(16) float g_WhT[FH * HHD];      // Wh transposed: (2048, 512)
__device__ __align__(16) float g_h[2][NB * HHD];     // double-buffered hidden state
__device__ unsigned g_count;                         // grid barrier counter

// packed fp32x2 ops (sm_100+)
__device__ __forceinline__ void ffma2(unsigned long long& d,
                                      unsigned long long a,
                                      unsigned long long b) {
    asm("fma.rn.f32x2 %0, %1, %2, %0;" : "+l"(d) : "l"(a), "l"(b));
}
__device__ __forceinline__ unsigned long long pack2(float x) {
    unsigned long long r;
    asm("mov.b64 %0, {%1, %1};" : "=l"(r) : "f"(x));
    return r;
}

// MUFU-based activations (EX2 + RCP), ~1e-6 accuracy, saturate cleanly.
__device__ __forceinline__ float fsig(float x) {
    return __fdividef(1.f, 1.f + __expf(-x));
}
__device__ __forceinline__ float ftanhf(float x) {
    return 1.f - __fdividef(2.f, __expf(2.f * x) + 1.f);
}

// ---------------- init: reset barrier counter + load h0 -----------------------
__global__ void init_kernel(const float* __restrict__ h0) {
    int i = blockIdx.x * blockDim.x + threadIdx.x;
    if (i == 0) g_count = 0u;
    if (i < NB * HHD) g_h[0][i] = h0[i];
}

// ---------------- transpose Wh (512,2048) -> WhT (2048,512) -------------------
__global__ void transpose_wh(const float* __restrict__ Wh) {
    int idx = blockIdx.x * blockDim.x + threadIdx.x;   // coalesced read
    int k = idx >> 11;
    int col = idx & 2047;
    g_WhT[col * HHD + k] = Wh[idx];
}

// ---------------- phase 1: xW = X @ Wx + b  (65536x2048x512 SGEMM) ------------
// (unchanged from R12 — passing, ~FFMA2 roofline)
__global__ __launch_bounds__(256, 2)
void gemm_xw(const float* __restrict__ X, const float* __restrict__ Wx,
             const float* __restrict__ bias) {
    __shared__ __align__(16) float As[8][128];
    __shared__ __align__(16) float Bs[8][128];

    const int tid  = threadIdx.x;
    const int row0 = blockIdx.y * 128;
    const int col0 = blockIdx.x * 128;

    const int aRow = tid >> 1;
    const int aCol = (tid & 1) * 4;
    const int bRow = tid >> 5;
    const int bCol = (tid & 31) * 4;

    const int tx = tid & 15;
    const int ty = tid >> 4;

    const float* Ap = X  + (size_t)(row0 + aRow) * DD + aCol;
    const float* Bp = Wx + (size_t)bRow * FH + col0 + bCol;

    unsigned long long acc2[8][4];
#pragma unroll
    for (int i = 0; i < 8; i++)
#pragma unroll
        for (int p = 0; p < 4; p++) acc2[i][p] = 0ull;

    for (int k0 = 0; k0 < DD; k0 += 8) {
        float4 av = __ldg((const float4*)(Ap + k0));
        float4 bv = __ldg((const float4*)(Bp + (size_t)k0 * FH));
        As[aCol + 0][aRow] = av.x;
        As[aCol + 1][aRow] = av.y;
        As[aCol + 2][aRow] = av.z;
        As[aCol + 3][aRow] = av.w;
        *(float4*)&Bs[bRow][bCol] = bv;
        __syncthreads();
#pragma unroll
        for (int k = 0; k < 8; k++) {
            float4 a0 = *(const float4*)&As[k][ty * 8];
            float4 a1 = *(const float4*)&As[k][ty * 8 + 4];
            ulonglong2 bp0 = *(const ulonglong2*)&Bs[k][tx * 4];
            ulonglong2 bp1 = *(const ulonglong2*)&Bs[k][64 + tx * 4];
            float ar[8] = {a0.x, a0.y, a0.z, a0.w, a1.x, a1.y, a1.z, a1.w};
#pragma unroll
            for (int i = 0; i < 8; i++) {
                unsigned long long aa = pack2(ar[i]);
                ffma2(acc2[i][0], aa, bp0.x);
                ffma2(acc2[i][1], aa, bp0.y);
                ffma2(acc2[i][2], aa, bp1.x);
                ffma2(acc2[i][3], aa, bp1.y);
            }
        }
        __syncthreads();
    }

    float4 bb0 = __ldg((const float4*)&bias[col0 + tx * 4]);
    float4 bb1 = __ldg((const float4*)&bias[col0 + 64 + tx * 4]);
#pragma unroll
    for (int i = 0; i < 8; i++) {
        int m  = row0 + ty * 8 + i;
        int tt = m & (TT - 1);
        int nn = m >> 10;
        float* orow = g_xw + ((size_t)(tt * NB + nn)) * FH + col0;
        union { unsigned long long u; float2 f; } p0, p1, p2, p3;
        p0.u = acc2[i][0]; p1.u = acc2[i][1];
        p2.u = acc2[i][2]; p3.u = acc2[i][3];
        float4 v0 = make_float4(p0.f.x + bb0.x, p0.f.y + bb0.y,
                                p1.f.x + bb0.z, p1.f.y + bb0.w);
        float4 v1 = make_float4(p2.f.x + bb1.x, p2.f.y + bb1.y,
                                p3.f.x + bb1.z, p3.f.y + bb1.w);
        *(float4*)(orow + tx * 4)      = v0;
        *(float4*)(orow + 64 + tx * 4) = v1;
    }
}

// ---------------- phase 2: persistent LSTM recurrence -------------------------
// 128 CTAs x 256 threads (1 CTA/SM, all co-resident). CTA b owns gate-local
// columns j0..j0+3 across all 4 gates. Thread (nl = tid>>2, jj = tid&3) owns
// element (nl, j0+jj): all 4 gate accumulators + persistent register cell c
// (R11/R12's proven ownership & activation math).
// NEW: no h smem tile. The dot loop reads h straight from L2 via __ldcg
// (paired 16B loads => full 32B sectors), W stays resident in smem (staged
// once, conflict-free broadcast). Barrier uses red.release.gpu + ld.acquire.gpu
// (no membar.gpu => no CCTL.IVALL L1 flush). Safe because all L1-cached reads
// (xw, WhT) are write-once data and all h reads bypass L1 (.cg).
#define HSTRIDE 516                               // 512 + 4 pad

__global__ __launch_bounds__(256, 1)
void lstm_kernel(float* __restrict__ out) {
    __shared__ __align__(16) float sw[16 * HSTRIDE];   // W tile, row = gate*4+col

    const int tid = threadIdx.x;
    const int nl  = tid >> 2;          // batch row 0..63
    const int jj  = tid & 3;           // column within CTA's 4
    const int j0  = blockIdx.x * 4;
    const int j   = j0 + jj;           // gate-local column 0..511

    // ---- stage Wh slice once: smem row r <-> (gate = r>>2, col = r&3) ----
    for (int i = tid; i < 2048; i += 256) {        // 16 rows x 128 float4
        int r  = i >> 7;
        int kq = (i & 127) * 4;
        int G  = (r >> 2) * HHD + j0 + (r & 3);    // WhT row (a-column)
        float4 v = __ldg((const float4*)&g_WhT[(size_t)G * HHD + kq]);
        *(float4*)&sw[r * HSTRIDE + kq] = v;
    }
    __syncthreads();                    // W tile visible before first dot

    const ulonglong2* wp0 = (const ulonglong2*)(sw + (0 * 4 + jj) * HSTRIDE);
    const ulonglong2* wp1 = (const ulonglong2*)(sw + (1 * 4 + jj) * HSTRIDE);
    const ulonglong2* wp2 = (const ulonglong2*)(sw + (2 * 4 + jj) * HSTRIDE);
    const ulonglong2* wp3 = (const ulonglong2*)(sw + (3 * 4 + jj) * HSTRIDE);

    float c = 0.f;
    int nb = 0;

    for (int t = 0; t < TT; t++) {
        // xW prefetch (L1/nc; fresh lines every step, consumed at step end)
        const size_t xb = ((size_t)(t * NB + nl)) * FH + j;
        float xw0 = __ldg(&g_xw[xb]);
        float xw1 = __ldg(&g_xw[xb + 512]);
        float xw2 = __ldg(&g_xw[xb + 1024]);
        float xw3 = __ldg(&g_xw[xb + 1536]);

        // ---- dot over k=512 straight from L2: per 8k, 2 LDG.cg.128 (full
        //      32B sectors/row) + 8 LDS.128 (W broadcast) + 16 FFMA2 ----
        const ulonglong2* hv =
            (const ulonglong2*)(g_h[nb] + (size_t)nl * HHD);
        unsigned long long a0 = 0ull, a1 = 0ull, a2 = 0ull, a3 = 0ull;
#pragma unroll 4
        for (int k8 = 0; k8 < 64; k8++) {
            ulonglong2 ha = __ldcg(hv + 2 * k8);
            ulonglong2 hb = __ldcg(hv + 2 * k8 + 1);
            ulonglong2 w0a = wp0[2 * k8], w0b = wp0[2 * k8 + 1];
            ulonglong2 w1a = wp1[2 * k8], w1b = wp1[2 * k8 + 1];
            ulonglong2 w2a = wp2[2 * k8], w2b = wp2[2 * k8 + 1];
            ulonglong2 w3a = wp3[2 * k8], w3b = wp3[2 * k8 + 1];
            ffma2(a0, ha.x, w0a.x); ffma2(a0, ha.y, w0a.y);
            ffma2(a0, hb.x, w0b.x); ffma2(a0, hb.y, w0b.y);
            ffma2(a1, ha.x, w1a.x); ffma2(a1, ha.y, w1a.y);
            ffma2(a1, hb.x, w1b.x); ffma2(a1, hb.y, w1b.y);
            ffma2(a2, ha.x, w2a.x); ffma2(a2, ha.y, w2a.y);
            ffma2(a2, hb.x, w2b.x); ffma2(a2, hb.y, w2b.y);
            ffma2(a3, ha.x, w3a.x); ffma2(a3, ha.y, w3a.y);
            ffma2(a3, hb.x, w3b.x); ffma2(a3, hb.y, w3b.y);
        }
        union { unsigned long long u; float2 f; } u0, u1, u2, u3;
        u0.u = a0; u1.u = a1; u2.u = a2; u3.u = a3;

        // gates (split order [i, f, o, g]) — same math as R11/R12
        float ai = xw0 + u0.f.x + u0.f.y;
        float af = xw1 + u1.f.x + u1.f.y;
        float ao = xw2 + u2.f.x + u2.f.y;
        float ag = xw3 + u3.f.x + u3.f.y;
        float ig = fsig(ai);
        float fg = fsig(af);
        float og = fsig(ao);
        float gg = ftanhf(ag);
        c = fg * c + ig * gg;
        float hn = og * ftanhf(c);

        out[((size_t)nl * TT + t) * HHD + j] = hn;
        g_h[nb ^ 1][nl * HHD + j] = hn;

        // ---- global barrier: bar -> release-RED -> acquire spin -> bar ----
        // (no membar.gpu: stores are visible at L2; release/acquire order them)
        __syncthreads();
        if (tid == 0) {
            asm volatile("red.release.gpu.add.u32 [%0], 1;"
                         :: "l"(&g_count) : "memory");
            unsigned tgt = (unsigned)(t + 1) * (unsigned)gridDim.x;
            unsigned v;
            do {
                asm volatile("ld.acquire.gpu.u32 %0, [%1];"
                             : "=r"(v) : "l"(&g_count) : "memory");
                if (v >= tgt) break;
                __nanosleep(32);
            } while (true);
        }
        __syncthreads();
        nb ^= 1;
    }
}

// ---------------- launch ------------------------------------------------------
extern "C" void kernel_launch(void* const* d_in, const int* in_sizes, int n_in,
                              void* d_out, int out_size) {
    (void)in_sizes; (void)n_in; (void)out_size;
    const float* x  = (const float*)d_in[0];   // (64,1024,512)
    const float* h0 = (const float*)d_in[1];   // (64,512)
    const float* Wx = (const float*)d_in[2];   // (512,2048)
    const float* Wh = (const float*)d_in[3];   // (512,2048)
    const float* b  = (const float*)d_in[4];   // (2048)
    float* out = (float*)d_out;                // (64,1024,512) fp32

    init_kernel<<<128, 256>>>(h0);
    transpose_wh<<<(DD * FH) / 256, 256>>>(Wh);
    gemm_xw<<<dim3(FH / 128, (NB * TT) / 128), 256>>>(x, Wx, b);
    lstm_kernel<<<128, 256>>>(out);
}

// round 15
// speedup vs baseline: 1.7184x; 1.5446x over previous
#include <cuda_runtime.h>
#include <math.h>

// Problem constants
#define NB   64      // batch N
#define TT   1024    // time steps
#define DD   512     // input dim
#define HHD  512     // hidden dim
#define FH   2048    // 4*H

// Grouping: 4 independent groups x 32 CTAs; each group owns 16 batch rows and
// holds ALL of Wh in its combined smem (128KB/CTA). No cross-group sync.
#define NGRP   4
#define GCTA   32                        // CTAs per group
#define GROWS  (NB / NGRP)               // 16 batch rows per group

// ---------------- device scratch (allocation-free rule: __device__ globals) ----
__device__ __align__(16) float g_xw[NB * TT * FH];   // xW+b, layout (t, n, col)
__device__ __align__(16) float g_WhT[FH * HHD];      // Wh transposed: (2048, 512)
__device__ __align__(16) float g_h[2][NB * HHD];     // double-buffered hidden state
__device__ __align__(128) unsigned g_gcnt[NGRP * 32]; // per-group barrier ctr (128B apart)

// packed fp32x2 ops (sm_100+)
__device__ __forceinline__ void ffma2(unsigned long long& d,
                                      unsigned long long a,
                                      unsigned long long b) {
    asm("fma.rn.f32x2 %0, %1, %2, %0;" : "+l"(d) : "l"(a), "l"(b));
}
__device__ __forceinline__ unsigned long long pack2(float x) {
    unsigned long long r;
    asm("mov.b64 %0, {%1, %1};" : "=l"(r) : "f"(x));
    return r;
}

// MUFU-based activations (EX2 + RCP), ~1e-6 accuracy, saturate cleanly.
__device__ __forceinline__ float fsig(float x) {
    return __fdividef(1.f, 1.f + __expf(-x));
}
__device__ __forceinline__ float ftanhf(float x) {
    return 1.f - __fdividef(2.f, __expf(2.f * x) + 1.f);
}

// ---------------- init: reset barrier counters + load h0 ----------------------
__global__ void init_kernel(const float* __restrict__ h0) {
    int i = blockIdx.x * blockDim.x + threadIdx.x;
    if (i < NGRP * 32) g_gcnt[i] = 0u;
    if (i < NB * HHD) g_h[0][i] = h0[i];
}

// ---------------- transpose Wh (512,2048) -> WhT (2048,512) -------------------
__global__ void transpose_wh(const float* __restrict__ Wh) {
    int idx = blockIdx.x * blockDim.x + threadIdx.x;   // coalesced read
    int k = idx >> 11;
    int col = idx & 2047;
    g_WhT[col * HHD + k] = Wh[idx];
}

// ---------------- phase 1: xW = X @ Wx + b  (65536x2048x512 SGEMM) ------------
// (unchanged from R12 — passing)
__global__ __launch_bounds__(256, 2)
void gemm_xw(const float* __restrict__ X, const float* __restrict__ Wx,
             const float* __restrict__ bias) {
    __shared__ __align__(16) float As[8][128];
    __shared__ __align__(16) float Bs[8][128];

    const int tid  = threadIdx.x;
    const int row0 = blockIdx.y * 128;
    const int col0 = blockIdx.x * 128;

    const int aRow = tid >> 1;
    const int aCol = (tid & 1) * 4;
    const int bRow = tid >> 5;
    const int bCol = (tid & 31) * 4;

    const int tx = tid & 15;
    const int ty = tid >> 4;

    const float* Ap = X  + (size_t)(row0 + aRow) * DD + aCol;
    const float* Bp = Wx + (size_t)bRow * FH + col0 + bCol;

    unsigned long long acc2[8][4];
#pragma unroll
    for (int i = 0; i < 8; i++)
#pragma unroll
        for (int p = 0; p < 4; p++) acc2[i][p] = 0ull;

    for (int k0 = 0; k0 < DD; k0 += 8) {
        float4 av = __ldg((const float4*)(Ap + k0));
        float4 bv = __ldg((const float4*)(Bp + (size_t)k0 * FH));
        As[aCol + 0][aRow] = av.x;
        As[aCol + 1][aRow] = av.y;
        As[aCol + 2][aRow] = av.z;
        As[aCol + 3][aRow] = av.w;
        *(float4*)&Bs[bRow][bCol] = bv;
        __syncthreads();
#pragma unroll
        for (int k = 0; k < 8; k++) {
            float4 a0 = *(const float4*)&As[k][ty * 8];
            float4 a1 = *(const float4*)&As[k][ty * 8 + 4];
            ulonglong2 bp0 = *(const ulonglong2*)&Bs[k][tx * 4];
            ulonglong2 bp1 = *(const ulonglong2*)&Bs[k][64 + tx * 4];
            float ar[8] = {a0.x, a0.y, a0.z, a0.w, a1.x, a1.y, a1.z, a1.w};
#pragma unroll
            for (int i = 0; i < 8; i++) {
                unsigned long long aa = pack2(ar[i]);
                ffma2(acc2[i][0], aa, bp0.x);
                ffma2(acc2[i][1], aa, bp0.y);
                ffma2(acc2[i][2], aa, bp1.x);
                ffma2(acc2[i][3], aa, bp1.y);
            }
        }
        __syncthreads();
    }

    float4 bb0 = __ldg((const float4*)&bias[col0 + tx * 4]);
    float4 bb1 = __ldg((const float4*)&bias[col0 + 64 + tx * 4]);
#pragma unroll
    for (int i = 0; i < 8; i++) {
        int m  = row0 + ty * 8 + i;
        int tt = m & (TT - 1);
        int nn = m >> 10;
        float* orow = g_xw + ((size_t)(tt * NB + nn)) * FH + col0;
        union { unsigned long long u; float2 f; } p0, p1, p2, p3;
        p0.u = acc2[i][0]; p1.u = acc2[i][1];
        p2.u = acc2[i][2]; p3.u = acc2[i][3];
        float4 v0 = make_float4(p0.f.x + bb0.x, p0.f.y + bb0.y,
                                p1.f.x + bb0.z, p1.f.y + bb0.w);
        float4 v1 = make_float4(p2.f.x + bb1.x, p2.f.y + bb1.y,
                                p3.f.x + bb1.z, p3.f.y + bb1.w);
        *(float4*)(orow + tx * 4)      = v0;
        *(float4*)(orow + 64 + tx * 4) = v1;
    }
}

// ---------------- phase 2: group-local persistent LSTM recurrence -------------
// 128 CTAs x 256 threads, 1 CTA/SM (all co-resident). CTA bid: group g = bid>>5
// (owns batch rows g*16..g*16+15), member m = bid&31 (owns gate-local columns
// c0 = m*16 .. c0+15 across all 4 gates; W slice = 64 WhT rows x 512 = 128KB,
// resident in smem). Thread (jc = tid>>4, r = tid&15) owns output element
// (row g*16+r, col c0+jc): 4 gate accumulators + register cell c (R11-proven
// tile & math). Per step: stage group's h (16x512 = 32KB) to smem, one sync,
// full-k dots, activations by ALL threads, group-local 32-CTA barrier
// (release-RED / acquire-load on a group-private counter).
#define HSTRIDE 516                               // 512 + 4 pad
#define HT_F    (GROWS * HSTRIDE)                 // 8256 floats (h tile)
#define WT_F    (64 * HSTRIDE)                    // 33024 floats (W tile)
#define LSTM_SMEM_BYTES ((HT_F + WT_F) * 4)       // 165,120 B

__global__ __launch_bounds__(256, 1)
void lstm_kernel(float* __restrict__ out) {
    extern __shared__ float sm[];
    float* sh = sm;               // h tile [16][516]
    float* sw = sm + HT_F;        // W tile [64][516], row = gate*16 + jc

    const int tid = threadIdx.x;
    const int jc  = tid >> 4;          // column within CTA's 16 (0..15)
    const int r   = tid & 15;          // group-local batch row (0..15)
    const int g   = blockIdx.x >> 5;   // group id 0..3
    const int m   = blockIdx.x & 31;   // member id 0..31
    const int c0  = m * 16;            // first gate-local column
    const int j   = c0 + jc;           // gate-local column 0..511
    const int n   = g * GROWS + r;     // global batch row

    unsigned* gcnt = &g_gcnt[g * 32];  // group-private counter (128B apart)

    // ---- stage W slice once: smem row rw = gate*16 + jc' ----
    for (int i = tid; i < 8192; i += 256) {        // 64 rows x 128 float4
        int rw = i >> 7;
        int kq = (i & 127) * 4;
        int G  = (rw >> 4) * HHD + c0 + (rw & 15); // WhT row (a-column)
        float4 v = __ldg((const float4*)&g_WhT[(size_t)G * HHD + kq]);
        *(float4*)&sw[rw * HSTRIDE + kq] = v;
    }
    __syncthreads();

    const ulonglong2* wp0 = (const ulonglong2*)(sw + (0 * 16 + jc) * HSTRIDE);
    const ulonglong2* wp1 = (const ulonglong2*)(sw + (1 * 16 + jc) * HSTRIDE);
    const ulonglong2* wp2 = (const ulonglong2*)(sw + (2 * 16 + jc) * HSTRIDE);
    const ulonglong2* wp3 = (const ulonglong2*)(sw + (3 * 16 + jc) * HSTRIDE);
    const ulonglong2* hq  = (const ulonglong2*)(sh + r * HSTRIDE);

    float c = 0.f;
    int nb = 0;

    for (int t = 0; t < TT; t++) {
        // xW prefetch (DRAM; consumed at step end)
        const size_t xb = ((size_t)(t * NB + n)) * FH + j;
        float xw0 = __ldg(&g_xw[xb]);
        float xw1 = __ldg(&g_xw[xb + 512]);
        float xw2 = __ldg(&g_xw[xb + 1024]);
        float xw3 = __ldg(&g_xw[xb + 1536]);

        // ---- stage group's h (32KB) into smem: 8 coalesced ld.cg/thread ----
        const float* hsrc = g_h[nb] + (size_t)g * GROWS * HHD;
#pragma unroll
        for (int u = 0; u < 8; u++) {
            int i = tid + u * 256;                    // float4 index 0..2047
            float4 v = __ldcg((const float4*)&hsrc[i * 4]);
            *(float4*)&sh[(i >> 7) * HSTRIDE + (i & 127) * 4] = v;
        }
        __syncthreads();

        // ---- full-k dot: 5 LDS.128 + 8 FFMA2 per 4k, 128 iters ----
        unsigned long long a0 = 0ull, a1 = 0ull, a2 = 0ull, a3 = 0ull;
#pragma unroll 8
        for (int kq = 0; kq < HHD / 4; kq++) {
            ulonglong2 hv = hq[kq];
            ulonglong2 v0 = wp0[kq];
            ulonglong2 v1 = wp1[kq];
            ulonglong2 v2 = wp2[kq];
            ulonglong2 v3 = wp3[kq];
            ffma2(a0, hv.x, v0.x); ffma2(a0, hv.y, v0.y);
            ffma2(a1, hv.x, v1.x); ffma2(a1, hv.y, v1.y);
            ffma2(a2, hv.x, v2.x); ffma2(a2, hv.y, v2.y);
            ffma2(a3, hv.x, v3.x); ffma2(a3, hv.y, v3.y);
        }
        union { unsigned long long u; float2 f; } u0, u1, u2, u3;
        u0.u = a0; u1.u = a1; u2.u = a2; u3.u = a3;

        // gates (split order [i, f, o, g]) — proven math
        float ai = xw0 + u0.f.x + u0.f.y;
        float af = xw1 + u1.f.x + u1.f.y;
        float ao = xw2 + u2.f.x + u2.f.y;
        float ag = xw3 + u3.f.x + u3.f.y;
        float ig = fsig(ai);
        float fg = fsig(af);
        float og = fsig(ao);
        float gg = ftanhf(ag);
        c = fg * c + ig * gg;
        float hn = og * ftanhf(c);

        out[((size_t)n * TT + t) * HHD + j] = hn;
        g_h[nb ^ 1][(size_t)n * HHD + j] = hn;

        // ---- group-local barrier: bar -> release-RED -> acquire spin -> bar --
        __syncthreads();
        if (tid == 0) {
            asm volatile("red.release.gpu.add.u32 [%0], 1;"
                         :: "l"(gcnt) : "memory");
            unsigned tgt = (unsigned)(t + 1) * (unsigned)GCTA;
            unsigned v;
            do {
                asm volatile("ld.acquire.gpu.u32 %0, [%1];"
                             : "=r"(v) : "l"(gcnt) : "memory");
                if (v >= tgt) break;
                __nanosleep(32);
            } while (true);
        }
        __syncthreads();
        nb ^= 1;
    }
}

// ---------------- launch ------------------------------------------------------
extern "C" void kernel_launch(void* const* d_in, const int* in_sizes, int n_in,
                              void* d_out, int out_size) {
    (void)in_sizes; (void)n_in; (void)out_size;
    const float* x  = (const float*)d_in[0];   // (64,1024,512)
    const float* h0 = (const float*)d_in[1];   // (64,512)
    const float* Wx = (const float*)d_in[2];   // (512,2048)
    const float* Wh = (const float*)d_in[3];   // (512,2048)
    const float* b  = (const float*)d_in[4];   // (2048)
    float* out = (float*)d_out;                // (64,1024,512) fp32

    cudaFuncSetAttribute(lstm_kernel,
                         cudaFuncAttributeMaxDynamicSharedMemorySize,
                         LSTM_SMEM_BYTES);

    init_kernel<<<128, 256>>>(h0);
    transpose_wh<<<(DD * FH) / 256, 256>>>(Wh);
    gemm_xw<<<dim3(FH / 128, (NB * TT) / 128), 256>>>(x, Wx, b);
    lstm_kernel<<<128, 256, LSTM_SMEM_BYTES>>>(out);
}